// round 3
// baseline (speedup 1.0000x reference)
#include <cuda_runtime.h>
#include <math.h>

// Problem shape (fixed by the reference): B=32, N=8192, D=128, fp32.
#define BATCH   32
#define NROWS   8192
#define DIM     128
#define CHUNKS  16
#define CHUNK   (NROWS / CHUNKS)   // 512 rows per CTA
#define WARPS   8                  // 256 threads
#define GROUP   4                  // rows per warp per iteration
#define NGROUPS (CHUNK / (WARPS * GROUP))  // 16

// Scratch (no allocations allowed -> __device__ globals)
__device__ float g_pm  [BATCH * CHUNKS];            // per-chunk max
__device__ float g_psum[BATCH * CHUNKS];            // per-chunk exp-sum
__device__ float g_pctx[BATCH * CHUNKS * DIM];      // per-chunk weighted ctx
__device__ float g_M   [BATCH];                     // global max per batch
__device__ float g_inv [BATCH];                     // 1/sum per batch

// ---------------------------------------------------------------------------
// Pass 1: one sweep over values. Warp-per-row dot, online softmax accumulation
// of (m, sum, ctx). Raw scores streamed to attn output. Per-CTA partials to
// global scratch.
// ---------------------------------------------------------------------------
__global__ void __launch_bounds__(256, 4)
attend_pass1(const float* __restrict__ q,
             const float* __restrict__ v,
             float* __restrict__ attn_raw)
{
    __shared__ float4 qs[DIM / 4];
    __shared__ float  sm_m[WARPS];
    __shared__ float  sm_sum[WARPS];
    __shared__ float  sm_ctx[WARPS][DIM];

    const int b     = blockIdx.y;
    const int chunk = blockIdx.x;
    const int tid   = threadIdx.x;
    const int w     = tid >> 5;
    const int l     = tid & 31;

    if (tid < DIM / 4)
        qs[tid] = reinterpret_cast<const float4*>(q + (size_t)b * DIM)[tid];
    __syncthreads();

    const float4 q4 = qs[l];
    const float4* __restrict__ vb =
        reinterpret_cast<const float4*>(v + (size_t)b * NROWS * DIM);
    const size_t rowq = DIM / 4;  // float4s per row

    // Rows for warp w, group g: base + g*(WARPS*GROUP) + k, k in [0,GROUP)
    const int base = chunk * CHUNK + w * GROUP;

    float  m   = -INFINITY;
    float  sum = 0.0f;
    float4 ctx = make_float4(0.f, 0.f, 0.f, 0.f);

    float4 vreg[GROUP], vnext[GROUP];

    // prefetch group 0
    {
        const size_t r = (size_t)base;
        #pragma unroll
        for (int k = 0; k < GROUP; k++)
            vreg[k] = vb[(r + k) * rowq + l];
    }

    #pragma unroll 1
    for (int g = 0; g < NGROUPS; g++) {
        if (g + 1 < NGROUPS) {
            const size_t r = (size_t)base + (size_t)(g + 1) * (WARPS * GROUP);
            #pragma unroll
            for (int k = 0; k < GROUP; k++)
                vnext[k] = vb[(r + k) * rowq + l];
        }

        // 4 independent dot-products + butterfly reductions (ILP across k)
        float sc[GROUP];
        #pragma unroll
        for (int k = 0; k < GROUP; k++) {
            float s = vreg[k].x * q4.x + vreg[k].y * q4.y
                    + vreg[k].z * q4.z + vreg[k].w * q4.w;
            #pragma unroll
            for (int o = 16; o > 0; o >>= 1)
                s += __shfl_xor_sync(0xffffffffu, s, o);
            sc[k] = s;  // uniform across the warp
        }

        // stream raw scores (vectorized: 4 consecutive rows, 16B aligned)
        if (l == 0) {
            const size_t r = (size_t)base + (size_t)g * (WARPS * GROUP);
            *reinterpret_cast<float4*>(attn_raw + (size_t)b * NROWS + r) =
                make_float4(sc[0], sc[1], sc[2], sc[3]);
        }

        // online softmax update (branch uniform across warp; new-max is rare)
        #pragma unroll
        for (int k = 0; k < GROUP; k++) {
            const float s = sc[k];
            float wgt;
            if (s <= m) {
                wgt = __expf(s - m);
            } else {
                const float c = __expf(m - s);
                sum  *= c;
                ctx.x *= c; ctx.y *= c; ctx.z *= c; ctx.w *= c;
                m = s;
                wgt = 1.0f;
            }
            sum  += wgt;
            ctx.x += wgt * vreg[k].x;
            ctx.y += wgt * vreg[k].y;
            ctx.z += wgt * vreg[k].z;
            ctx.w += wgt * vreg[k].w;
        }

        #pragma unroll
        for (int k = 0; k < GROUP; k++)
            vreg[k] = vnext[k];
    }

    // CTA-level merge of 8 warp-partials
    if (l == 0) { sm_m[w] = m; sm_sum[w] = sum; }
    reinterpret_cast<float4*>(sm_ctx[w])[l] = ctx;
    __syncthreads();

    if (tid < DIM) {
        float M = sm_m[0];
        #pragma unroll
        for (int i = 1; i < WARPS; i++) M = fmaxf(M, sm_m[i]);

        float c = 0.0f;
        #pragma unroll
        for (int i = 0; i < WARPS; i++)
            c += sm_ctx[i][tid] * __expf(sm_m[i] - M);

        const int pidx = b * CHUNKS + chunk;
        g_pctx[(size_t)pidx * DIM + tid] = c;

        if (tid == 0) {
            float st = 0.0f;
            #pragma unroll
            for (int i = 0; i < WARPS; i++)
                st += sm_sum[i] * __expf(sm_m[i] - M);
            g_pm[pidx]   = M;
            g_psum[pidx] = st;
        }
    }
}

// ---------------------------------------------------------------------------
// Pass 2: combine 16 chunk-partials per batch -> context output + (M, 1/sum)
// ---------------------------------------------------------------------------
__global__ void __launch_bounds__(128)
attend_pass2(float* __restrict__ ctx_out)
{
    const int b = blockIdx.x;
    const int j = threadIdx.x;

    float M = -INFINITY;
    #pragma unroll
    for (int c = 0; c < CHUNKS; c++)
        M = fmaxf(M, g_pm[b * CHUNKS + c]);

    float s = 0.0f, acc = 0.0f;
    #pragma unroll
    for (int c = 0; c < CHUNKS; c++) {
        const float f = __expf(g_pm[b * CHUNKS + c] - M);
        s   += g_psum[b * CHUNKS + c] * f;
        acc += g_pctx[(size_t)(b * CHUNKS + c) * DIM + j] * f;
    }

    ctx_out[(size_t)b * DIM + j] = acc / s;
    if (j == 0) {
        g_M[b]   = M;
        g_inv[b] = 1.0f / s;
    }
}

// ---------------------------------------------------------------------------
// Pass 3: normalize raw scores in place -> attn
// ---------------------------------------------------------------------------
__global__ void __launch_bounds__(256)
attend_pass3(float* __restrict__ attn)
{
    const int i = blockIdx.x * blockDim.x + threadIdx.x;  // < BATCH*NROWS
    const int b = i >> 13;                                 // NROWS = 8192
    const float sc = attn[i];
    attn[i] = __expf(sc - g_M[b]) * g_inv[b];
}

// ---------------------------------------------------------------------------
extern "C" void kernel_launch(void* const* d_in, const int* in_sizes, int n_in,
                              void* d_out, int out_size)
{
    // Identify inputs by size (queries: 32*1*128 = 4096; values: 32*8192*128)
    const float* q;
    const float* v;
    if (in_sizes[0] == BATCH * DIM) {
        q = (const float*)d_in[0];
        v = (const float*)d_in[1];
    } else {
        q = (const float*)d_in[1];
        v = (const float*)d_in[0];
    }

    float* attn = (float*)d_out;                       // [32, 8192]
    float* ctx  = (float*)d_out + (size_t)BATCH * NROWS;  // [32, 128]

    dim3 grid1(CHUNKS, BATCH);
    attend_pass1<<<grid1, 256>>>(q, v, attn);
    attend_pass2<<<BATCH, 128>>>(ctx);
    attend_pass3<<<(BATCH * NROWS) / 256, 256>>>(attn);
}